// round 1
// baseline (speedup 1.0000x reference)
#include <cuda_runtime.h>
#include <cstdint>

// ---------------- problem constants ----------------
#define NN 100000
#define EE 1600000
#define XD 64
#define HD 128

// ---------------- scratch (device globals; no allocations allowed) ----------
__device__ float  g_h0[(size_t)NN * HD];        // relu(x@w1+b1)
__device__ float  g_sums[(size_t)NN * HD];      // scatter-add accumulator
__device__ float  g_cnt[NN];                    // edge counts (float)
__device__ float  g_p1[(size_t)NN * 256];       // pre-BN layer1
__device__ float  g_p2[(size_t)NN * 1024];      // pre-BN layer2
__device__ float  g_p3[(size_t)NN * 256];       // pre-BN layer3
__device__ float  g_bcat[256 * 128];            // [wl; wr]
__device__ double g_cs[1024];                   // column sums
__device__ double g_cq[1024];                   // column sumsq
__device__ float  g_scale[1024];                // BN fused scale
__device__ float  g_shift[1024];                // BN fused shift
__device__ int    g_is64;                       // edge_index dtype flag

// ---------------- small utility kernels ----------------
__global__ void zero_f(float* p, int n) {
    int i = (blockIdx.x * blockDim.x + threadIdx.x) * 4;
    if (i + 3 < n) { *(float4*)(p + i) = make_float4(0.f, 0.f, 0.f, 0.f); }
    else { for (; i < n; i++) p[i] = 0.f; }
}

__global__ void set_flag(int* f) { *f = 1; }

__global__ void detect64(const unsigned int* w, int* flag) {
    int t = blockIdx.x * blockDim.x + threadIdx.x;   // t in [0,4096)
    if (w[2 * t + 1] != 0u) atomicExch(flag, 0);
}

__global__ void build_bcat(const float* __restrict__ wl, const float* __restrict__ wr,
                           float* __restrict__ bcat) {
    int i = blockIdx.x * blockDim.x + threadIdx.x;   // 32768 total
    if (i < 16384) bcat[i] = wl[i];
    else if (i < 32768) bcat[i] = wr[i - 16384];
}

__global__ void zstats(double* cs, double* cq) {
    int i = blockIdx.x * blockDim.x + threadIdx.x;
    if (i < 1024) { cs[i] = 0.0; cq[i] = 0.0; }
}

// ---------------- edge scatter (SAGE aggregation) ----------------
__global__ void edge_kernel(const void* __restrict__ ei,
                            const float* __restrict__ h0,
                            float* __restrict__ sums,
                            float* __restrict__ cnt,
                            const int* __restrict__ flag) {
    int warp = (blockIdx.x * blockDim.x + threadIdx.x) >> 5;
    int lane = threadIdx.x & 31;
    if (warp >= EE) return;
    long long src, dst;
    if (*flag) {
        const long long* p = (const long long*)ei;
        src = p[warp]; dst = p[EE + warp];
    } else {
        const int* p = (const int*)ei;
        src = p[warp]; dst = p[EE + warp];
    }
    float4 v = *(const float4*)(h0 + src * HD + lane * 4);
    float* d = sums + dst * HD + lane * 4;
    asm volatile("red.global.add.v4.f32 [%0], {%1, %2, %3, %4};"
                 :: "l"(d), "f"(v.x), "f"(v.y), "f"(v.z), "f"(v.w) : "memory");
    if (lane == 0) atomicAdd(cnt + dst, 1.0f);
}

// ---------------- column stats (for BatchNorm) ----------------
__global__ void colstats(const float* __restrict__ g, int ncols,
                         double* __restrict__ cs, double* __restrict__ cq) {
    int col = blockIdx.x * 256 + threadIdx.x;        // gridDim.x = ncols/256
    int slab = blockIdx.y, nslab = gridDim.y;
    int r0 = (int)((long long)NN * slab / nslab);
    int r1 = (int)((long long)NN * (slab + 1) / nslab);
    double s = 0.0, q = 0.0;
    for (int r = r0; r < r1; r++) {
        float v = g[(long long)r * ncols + col];
        s += (double)v;
        q += (double)v * (double)v;
    }
    atomicAdd(&cs[col], s);
    atomicAdd(&cq[col], q);
}

__global__ void fin_bn(const double* __restrict__ cs, const double* __restrict__ cq,
                       const float* __restrict__ gm, const float* __restrict__ bt,
                       float* __restrict__ sc, float* __restrict__ sh, int ncols) {
    int c = blockIdx.x * blockDim.x + threadIdx.x;
    if (c < ncols) {
        double mean = cs[c] * (1.0 / (double)NN);
        double var  = cq[c] * (1.0 / (double)NN) - mean * mean;
        if (var < 0.0) var = 0.0;
        float rstd = (float)(1.0 / sqrt(var + 1e-5));
        float s = gm[c] * rstd;
        sc[c] = s;
        sh[c] = bt[c] - (float)mean * s;
    }
}

// ---------------- main SIMT fp32 GEMM ----------------
// C[M,N] = transform(A)[M,K] @ B[K,N] + bias[N]  (optional relu epilogue)
// MODE 0: plain A
// MODE 1: a = relu(a*sc[k] + sh[k])     (fused BN of previous layer)
// MODE 2: k<128 -> sums[row,k]/max(cnt,1);  k>=128 -> aux(h0)[row,k-128]
#define BM 128
#define BN 64
#define BK 16

template<int MODE, int RELU_EPI>
__global__ __launch_bounds__(256, 2)
void gemm_k(const float* __restrict__ A, const float* __restrict__ B,
            const float* __restrict__ bias, float* __restrict__ C,
            int M, int K, int N,
            const float* __restrict__ sc, const float* __restrict__ sh,
            const float* __restrict__ aux, const float* __restrict__ cntp) {
    __shared__ __align__(16) float As[BK][BM + 4];
    __shared__ __align__(16) float Bs[BK][BN];
    int tid = threadIdx.x;
    int tx = tid & 15, ty = tid >> 4;
    int m0 = blockIdx.y * BM;
    int n0 = blockIdx.x * BN;

    float acc[8][4];
#pragma unroll
    for (int i = 0; i < 8; i++)
#pragma unroll
        for (int j = 0; j < 4; j++) acc[i][j] = 0.f;

    for (int k0 = 0; k0 < K; k0 += BK) {
        // load A tile (2048 floats as 512 float4s, 2 per thread), transform on load
#pragma unroll
        for (int l = 0; l < 2; l++) {
            int idx = tid + l * 256;
            int row = idx >> 2, kq = idx & 3;
            int grow = m0 + row;
            float4 v = make_float4(0.f, 0.f, 0.f, 0.f);
            if (grow < M) {
                if (MODE == 2) {
                    if (k0 < 128) {
                        v = *(const float4*)(A + (long long)grow * 128 + k0 + kq * 4);
                        float ic = 1.0f / fmaxf(cntp[grow], 1.0f);
                        v.x *= ic; v.y *= ic; v.z *= ic; v.w *= ic;
                    } else {
                        v = *(const float4*)(aux + (long long)grow * 128 + (k0 - 128) + kq * 4);
                    }
                } else {
                    v = *(const float4*)(A + (long long)grow * K + k0 + kq * 4);
                    if (MODE == 1) {
                        float4 s4 = *(const float4*)(sc + k0 + kq * 4);
                        float4 h4 = *(const float4*)(sh + k0 + kq * 4);
                        v.x = fmaxf(fmaf(v.x, s4.x, h4.x), 0.f);
                        v.y = fmaxf(fmaf(v.y, s4.y, h4.y), 0.f);
                        v.z = fmaxf(fmaf(v.z, s4.z, h4.z), 0.f);
                        v.w = fmaxf(fmaf(v.w, s4.w, h4.w), 0.f);
                    }
                }
            }
            As[kq * 4 + 0][row] = v.x;
            As[kq * 4 + 1][row] = v.y;
            As[kq * 4 + 2][row] = v.z;
            As[kq * 4 + 3][row] = v.w;
        }
        // load B tile (16x64)
        {
            int kr = tid >> 4, nq = tid & 15;
            float4 v = *(const float4*)(B + (long long)(k0 + kr) * N + n0 + nq * 4);
            *(float4*)&Bs[kr][nq * 4] = v;
        }
        __syncthreads();
#pragma unroll
        for (int kk = 0; kk < BK; kk++) {
            float4 a0 = *(const float4*)&As[kk][ty * 4];
            float4 a1 = *(const float4*)&As[kk][64 + ty * 4];
            float4 b  = *(const float4*)&Bs[kk][tx * 4];
            float av[8] = {a0.x, a0.y, a0.z, a0.w, a1.x, a1.y, a1.z, a1.w};
            float bv[4] = {b.x, b.y, b.z, b.w};
#pragma unroll
            for (int i = 0; i < 8; i++)
#pragma unroll
                for (int j = 0; j < 4; j++)
                    acc[i][j] = fmaf(av[i], bv[j], acc[i][j]);
        }
        __syncthreads();
    }

    float4 bb = *(const float4*)(bias + n0 + tx * 4);
#pragma unroll
    for (int i = 0; i < 8; i++) {
        int row = m0 + ((i < 4) ? (ty * 4 + i) : (64 + ty * 4 + (i - 4)));
        if (row < M) {
            float4 o;
            o.x = acc[i][0] + bb.x; o.y = acc[i][1] + bb.y;
            o.z = acc[i][2] + bb.z; o.w = acc[i][3] + bb.w;
            if (RELU_EPI) {
                o.x = fmaxf(o.x, 0.f); o.y = fmaxf(o.y, 0.f);
                o.z = fmaxf(o.z, 0.f); o.w = fmaxf(o.w, 0.f);
            }
            *(float4*)(C + (long long)row * N + n0 + tx * 4) = o;
        }
    }
}

// ---------------- final layer: BN+ReLU(g3) -> penultimate + logits ----------
__global__ __launch_bounds__(256)
void final_kernel(const float* __restrict__ g3,
                  const float* __restrict__ sc, const float* __restrict__ sh,
                  const float* __restrict__ hw4, const float* __restrict__ hb4,
                  float* __restrict__ pen, float* __restrict__ logits) {
    __shared__ float w4s[256 * 16];
    __shared__ float at[16 * 256];
    int t = threadIdx.x;
    for (int i = t; i < 4096; i += 256) w4s[i] = hw4[i];
    long long r0 = (long long)blockIdx.x * 16;
#pragma unroll
    for (int i = 0; i < 16; i++) {
        float v = g3[(r0 + i) * 256 + t];
        v = fmaxf(fmaf(v, sc[t], sh[t]), 0.f);
        at[i * 256 + t] = v;
        pen[(r0 + i) * 256 + t] = v;
    }
    __syncthreads();
    int r = t >> 4, c = t & 15;
    float acc = hb4[c];
#pragma unroll 8
    for (int k = 0; k < 256; k++)
        acc = fmaf(at[r * 256 + k], w4s[k * 16 + c], acc);
    logits[(r0 + r) * 16 + c] = acc;
}

// ---------------- launch ----------------
extern "C" void kernel_launch(void* const* d_in, const int* in_sizes, int n_in,
                              void* d_out, int out_size) {
    const float* x   = (const float*)d_in[0];
    const void*  ei  = d_in[1];
    const float* w1  = (const float*)d_in[2];
    const float* b1  = (const float*)d_in[3];
    const float* wl  = (const float*)d_in[4];
    const float* bl  = (const float*)d_in[5];
    const float* wr  = (const float*)d_in[6];
    const float* hw1 = (const float*)d_in[7];
    const float* hb1 = (const float*)d_in[8];
    const float* ga1 = (const float*)d_in[9];
    const float* be1 = (const float*)d_in[10];
    const float* hw2 = (const float*)d_in[11];
    const float* hb2 = (const float*)d_in[12];
    const float* ga2 = (const float*)d_in[13];
    const float* be2 = (const float*)d_in[14];
    const float* hw3 = (const float*)d_in[15];
    const float* hb3 = (const float*)d_in[16];
    const float* ga3 = (const float*)d_in[17];
    const float* be3 = (const float*)d_in[18];
    const float* hw4 = (const float*)d_in[19];
    const float* hb4 = (const float*)d_in[20];

    float* out_logits = (float*)d_out;                       // [N,16]
    float* out_pen    = (float*)d_out + (size_t)NN * 16;     // [N,256]
    float* out_feat   = (float*)d_out + (size_t)NN * (16 + 256); // [N,128]

    float *h0, *sums, *cnt, *p1, *p2, *p3, *bcat, *sc, *sh;
    double *cs, *cq;
    int* flag;
    cudaGetSymbolAddress((void**)&h0,   g_h0);
    cudaGetSymbolAddress((void**)&sums, g_sums);
    cudaGetSymbolAddress((void**)&cnt,  g_cnt);
    cudaGetSymbolAddress((void**)&p1,   g_p1);
    cudaGetSymbolAddress((void**)&p2,   g_p2);
    cudaGetSymbolAddress((void**)&p3,   g_p3);
    cudaGetSymbolAddress((void**)&bcat, g_bcat);
    cudaGetSymbolAddress((void**)&sc,   g_scale);
    cudaGetSymbolAddress((void**)&sh,   g_shift);
    cudaGetSymbolAddress((void**)&cs,   g_cs);
    cudaGetSymbolAddress((void**)&cq,   g_cq);
    cudaGetSymbolAddress((void**)&flag, g_is64);

    const int M = NN;
    dim3 blk(256);

    // dtype detection for edge_index (int64 vs int32)
    set_flag<<<1, 1>>>(flag);
    detect64<<<16, 256>>>((const unsigned int*)ei, flag);

    // zero scatter accumulators
    zero_f<<<(NN * HD / 4 + 255) / 256, blk>>>(sums, NN * HD);
    zero_f<<<(NN / 4 + 255) / 256, blk>>>(cnt, NN);

    // G1: h0 = relu(x@w1 + b1)   [M,64]@[64,128]
    {
        dim3 g(128 / BN, (M + BM - 1) / BM);
        gemm_k<0, 1><<<g, blk>>>(x, w1, b1, h0, M, XD, HD,
                                 nullptr, nullptr, nullptr, nullptr);
    }

    // edge scatter: sums += h0[src] at dst; cnt[dst] += 1
    edge_kernel<<<EE / 8, blk>>>(ei, h0, sums, cnt, flag);

    // Bcat = [wl; wr]  [256,128]
    build_bcat<<<128, blk>>>(wl, wr, bcat);

    // G2: out_feat = [aggr | h0] @ Bcat + bl   [M,256]@[256,128]
    {
        dim3 g(128 / BN, (M + BM - 1) / BM);
        gemm_k<2, 0><<<g, blk>>>(sums, bcat, bl, out_feat, M, 256, HD,
                                 nullptr, nullptr, h0, cnt);
    }

    // G3: p1 = out_feat @ hw1 + hb1  [M,128]@[128,256]
    {
        dim3 g(256 / BN, (M + BM - 1) / BM);
        gemm_k<0, 0><<<g, blk>>>(out_feat, hw1, hb1, p1, M, 128, 256,
                                 nullptr, nullptr, nullptr, nullptr);
    }
    // BN stats layer 1
    zstats<<<4, blk>>>(cs, cq);
    { dim3 g(256 / 256, 128); colstats<<<g, blk>>>(p1, 256, cs, cq); }
    fin_bn<<<1, 256>>>(cs, cq, ga1, be1, sc, sh, 256);

    // G4: p2 = relu(bn(p1)) @ hw2 + hb2  [M,256]@[256,1024]
    {
        dim3 g(1024 / BN, (M + BM - 1) / BM);
        gemm_k<1, 0><<<g, blk>>>(p1, hw2, hb2, p2, M, 256, 1024,
                                 sc, sh, nullptr, nullptr);
    }
    // BN stats layer 2
    zstats<<<4, blk>>>(cs, cq);
    { dim3 g(1024 / 256, 128); colstats<<<g, blk>>>(p2, 1024, cs, cq); }
    fin_bn<<<4, 256>>>(cs, cq, ga2, be2, sc, sh, 1024);

    // G5: p3 = relu(bn(p2)) @ hw3 + hb3  [M,1024]@[1024,256]
    {
        dim3 g(256 / BN, (M + BM - 1) / BM);
        gemm_k<1, 0><<<g, blk>>>(p2, hw3, hb3, p3, M, 1024, 256,
                                 sc, sh, nullptr, nullptr);
    }
    // BN stats layer 3
    zstats<<<4, blk>>>(cs, cq);
    { dim3 g(256 / 256, 128); colstats<<<g, blk>>>(p3, 256, cs, cq); }
    fin_bn<<<1, 256>>>(cs, cq, ga3, be3, sc, sh, 256);

    // Final: penultimate = relu(bn(p3)); logits = penultimate @ hw4 + hb4
    final_kernel<<<NN / 16, blk>>>(p3, sc, sh, hw4, hb4, out_pen, out_logits);
}

// round 3
// speedup vs baseline: 1.5738x; 1.5738x over previous
#include <cuda_runtime.h>
#include <cuda_bf16.h>
#include <cstdint>

// ---------------- problem constants ----------------
#define NN 100000
#define EE 1600000

// ---------------- scratch (device globals) ----------------
__device__ float  g_h0[(size_t)NN * 128];
__device__ float  g_sums[(size_t)NN * 128];
__device__ float  g_cnt[NN];
__device__ float  g_p1[(size_t)NN * 256];
__device__ float  g_p2[(size_t)NN * 1024];
__device__ float  g_p3[(size_t)NN * 256];
__device__ double g_cs[1024];
__device__ double g_cq[1024];
__device__ float  g_scale[1024];
__device__ float  g_shift[1024];
__device__ int    g_is64;
// transposed + bf16-split weights, stored [N, K] row-major
__device__ __nv_bfloat16 g_b1h[128 * 64],   g_b1l[128 * 64];     // w1
__device__ __nv_bfloat16 g_b2h[128 * 256],  g_b2l[128 * 256];    // [wl; wr]
__device__ __nv_bfloat16 g_b3h[256 * 128],  g_b3l[256 * 128];    // hw1
__device__ __nv_bfloat16 g_b4h[1024 * 256], g_b4l[1024 * 256];   // hw2
__device__ __nv_bfloat16 g_b5h[256 * 1024], g_b5l[256 * 1024];   // hw3

// ---------------- helpers ----------------
__device__ __forceinline__ uint32_t smem_u32(const void* p) {
    uint32_t a;
    asm("{ .reg .u64 t; cvta.to.shared.u64 t, %1; cvt.u32.u64 %0, t; }" : "=r"(a) : "l"(p));
    return a;
}
#define LDSM4(R, addr) \
    asm volatile("ldmatrix.sync.aligned.m8n8.x4.shared.b16 {%0,%1,%2,%3}, [%4];" \
        : "=r"((R)[0]), "=r"((R)[1]), "=r"((R)[2]), "=r"((R)[3]) : "r"(addr))

__device__ __forceinline__ void mma_bf16(float* c, const uint32_t* a, const uint32_t* b) {
    asm volatile("mma.sync.aligned.m16n8k16.row.col.f32.bf16.bf16.f32 "
        "{%0,%1,%2,%3}, {%4,%5,%6,%7}, {%8,%9}, {%0,%1,%2,%3};"
        : "+f"(c[0]), "+f"(c[1]), "+f"(c[2]), "+f"(c[3])
        : "r"(a[0]), "r"(a[1]), "r"(a[2]), "r"(a[3]), "r"(b[0]), "r"(b[1]));
}
__device__ __forceinline__ void split_bf(float v, uint16_t& h, uint16_t& l) {
    __nv_bfloat16 hb = __float2bfloat16(v);
    __nv_bfloat16 lb = __float2bfloat16(v - __bfloat162float(hb));
    h = __bfloat16_as_ushort(hb);
    l = __bfloat16_as_ushort(lb);
}

// ---------------- small utility kernels ----------------
__global__ void zero_f(float* p, int n) {
    int i = (blockIdx.x * blockDim.x + threadIdx.x) * 4;
    if (i + 3 < n) { *(float4*)(p + i) = make_float4(0.f, 0.f, 0.f, 0.f); }
    else { for (; i < n; i++) p[i] = 0.f; }
}
__global__ void set_flag(int* f) { *f = 1; }
__global__ void detect64(const unsigned int* w, int* flag) {
    int t = blockIdx.x * blockDim.x + threadIdx.x;
    if (w[2 * t + 1] != 0u) atomicExch(flag, 0);
}
__global__ void zstats(double* cs, double* cq) {
    int i = blockIdx.x * blockDim.x + threadIdx.x;
    if (i < 1024) { cs[i] = 0.0; cq[i] = 0.0; }
}
// transpose + bf16-split: W[K,N] row-major -> bh/bl [N,K]
__global__ void tsplit(const float* __restrict__ W, __nv_bfloat16* __restrict__ bh,
                       __nv_bfloat16* __restrict__ bl, int K, int N) {
    int idx = blockIdx.x * blockDim.x + threadIdx.x;
    if (idx >= N * K) return;
    int n = idx / K, k = idx % K;
    float v = W[(size_t)k * N + n];
    __nv_bfloat16 h = __float2bfloat16(v);
    bh[idx] = h;
    bl[idx] = __float2bfloat16(v - __bfloat162float(h));
}
__global__ void tsplit_cat(const float* __restrict__ wl, const float* __restrict__ wr,
                           __nv_bfloat16* __restrict__ bh, __nv_bfloat16* __restrict__ bl) {
    int idx = blockIdx.x * blockDim.x + threadIdx.x;   // < 128*256
    int n = idx / 256, k = idx % 256;
    float v = (k < 128) ? wl[k * 128 + n] : wr[(k - 128) * 128 + n];
    __nv_bfloat16 h = __float2bfloat16(v);
    bh[idx] = h;
    bl[idx] = __float2bfloat16(v - __bfloat162float(h));
}

// ---------------- edge scatter ----------------
__global__ void edge_kernel(const void* __restrict__ ei, const float* __restrict__ h0,
                            float* __restrict__ sums, float* __restrict__ cnt,
                            const int* __restrict__ flag) {
    int warp = (blockIdx.x * blockDim.x + threadIdx.x) >> 5;
    int lane = threadIdx.x & 31;
    if (warp >= EE) return;
    long long src, dst;
    if (*flag) {
        const long long* p = (const long long*)ei;
        src = p[warp]; dst = p[EE + warp];
    } else {
        const int* p = (const int*)ei;
        src = p[warp]; dst = p[EE + warp];
    }
    float4 v = *(const float4*)(h0 + src * 128 + lane * 4);
    float* d = sums + dst * 128 + lane * 4;
    asm volatile("red.global.add.v4.f32 [%0], {%1, %2, %3, %4};"
                 :: "l"(d), "f"(v.x), "f"(v.y), "f"(v.z), "f"(v.w) : "memory");
    if (lane == 0) atomicAdd(cnt + dst, 1.0f);
}

// ---------------- column stats / BN ----------------
__global__ void colstats(const float* __restrict__ g, int ncols,
                         double* __restrict__ cs, double* __restrict__ cq) {
    int col = blockIdx.x * 256 + threadIdx.x;
    int slab = blockIdx.y, nslab = gridDim.y;
    int r0 = (int)((long long)NN * slab / nslab);
    int r1 = (int)((long long)NN * (slab + 1) / nslab);
    double s = 0.0, q = 0.0;
    for (int r = r0; r < r1; r++) {
        float v = g[(size_t)r * ncols + col];
        s += (double)v; q += (double)v * (double)v;
    }
    atomicAdd(&cs[col], s);
    atomicAdd(&cq[col], q);
}
__global__ void fin_bn(const double* __restrict__ cs, const double* __restrict__ cq,
                       const float* __restrict__ gm, const float* __restrict__ bt,
                       float* __restrict__ sc, float* __restrict__ sh, int ncols) {
    int c = blockIdx.x * blockDim.x + threadIdx.x;
    if (c < ncols) {
        double mean = cs[c] * (1.0 / (double)NN);
        double var  = cq[c] * (1.0 / (double)NN) - mean * mean;
        if (var < 0.0) var = 0.0;
        float rstd = (float)(1.0 / sqrt(var + 1e-5));
        float s = gm[c] * rstd;
        sc[c] = s;
        sh[c] = bt[c] - (float)mean * s;
    }
}

// ---------------- mma.sync bf16x3 GEMM ----------------
// C[M,N] = T(A)[M,K] @ Bsplit^T + bias;  Bh/Bl stored [N,K] row-major bf16.
// MODE 0: plain A | MODE 1: relu(a*sc[k]+sh[k]) | MODE 2: k<128: A(sums)/cnt; k>=128: aux
// Block tile 128x128, BK=32; 8 warps: warp (wid&3)->M 32 rows, (wid>>2)->N 64 cols.
#define LDA 40   // smem row stride in halves (32 + 8 pad)

template<int MODE, int RELU>
__global__ __launch_bounds__(256, 2)
void mgemm(const float* __restrict__ A, const __nv_bfloat16* __restrict__ Bh,
           const __nv_bfloat16* __restrict__ Bl, const float* __restrict__ bias,
           float* __restrict__ C, int M, int K, int N,
           const float* __restrict__ sc, const float* __restrict__ sh,
           const float* __restrict__ aux, const float* __restrict__ cnt) {
    __shared__ __align__(16) uint16_t sAh[128 * LDA];
    __shared__ __align__(16) uint16_t sAl[128 * LDA];
    __shared__ __align__(16) uint16_t sBh[128 * LDA];
    __shared__ __align__(16) uint16_t sBl[128 * LDA];

    const int tid = threadIdx.x, lane = tid & 31, wid = tid >> 5;
    const int wm = (wid & 3) * 32;
    const int wn = (wid >> 2) * 64;
    const int m0 = blockIdx.y * 128, n0 = blockIdx.x * 128;

    const uint32_t ah_b = smem_u32(sAh);
    const uint32_t al_b = smem_u32(sAl);
    const uint32_t bh_b = smem_u32(sBh);
    const uint32_t bl_b = smem_u32(sBl);

    float acc[2][8][4];
#pragma unroll
    for (int i = 0; i < 2; i++)
#pragma unroll
        for (int j = 0; j < 8; j++)
#pragma unroll
            for (int q = 0; q < 4; q++) acc[i][j][q] = 0.f;

    for (int k0 = 0; k0 < K; k0 += 32) {
        // ---- A: 128 rows x 32 cols fp32 -> split bf16 hi/lo ----
#pragma unroll
        for (int l = 0; l < 4; l++) {
            int pos = tid + l * 256;
            int row = pos >> 3, cq = pos & 7;
            int grow = m0 + row;
            float4 v = make_float4(0.f, 0.f, 0.f, 0.f);
            if (grow < M) {
                if (MODE == 2) {
                    if (k0 < 128) {
                        v = *(const float4*)(A + (size_t)grow * 128 + k0 + cq * 4);
                        float ic = 1.f / fmaxf(cnt[grow], 1.f);
                        v.x *= ic; v.y *= ic; v.z *= ic; v.w *= ic;
                    } else {
                        v = *(const float4*)(aux + (size_t)grow * 128 + (k0 - 128) + cq * 4);
                    }
                } else {
                    v = *(const float4*)(A + (size_t)grow * K + k0 + cq * 4);
                    if (MODE == 1) {
                        float4 s4 = *(const float4*)(sc + k0 + cq * 4);
                        float4 h4 = *(const float4*)(sh + k0 + cq * 4);
                        v.x = fmaxf(fmaf(v.x, s4.x, h4.x), 0.f);
                        v.y = fmaxf(fmaf(v.y, s4.y, h4.y), 0.f);
                        v.z = fmaxf(fmaf(v.z, s4.z, h4.z), 0.f);
                        v.w = fmaxf(fmaf(v.w, s4.w, h4.w), 0.f);
                    }
                }
            }
            uint16_t h0_, h1_, h2_, h3_, l0_, l1_, l2_, l3_;
            split_bf(v.x, h0_, l0_); split_bf(v.y, h1_, l1_);
            split_bf(v.z, h2_, l2_); split_bf(v.w, h3_, l3_);
            int off = row * LDA + cq * 4;
            *(uint2*)&sAh[off] = make_uint2((uint32_t)h0_ | ((uint32_t)h1_ << 16),
                                            (uint32_t)h2_ | ((uint32_t)h3_ << 16));
            *(uint2*)&sAl[off] = make_uint2((uint32_t)l0_ | ((uint32_t)l1_ << 16),
                                            (uint32_t)l2_ | ((uint32_t)l3_ << 16));
        }
        // ---- B: 128 rows x 32 cols bf16 (pre-split) ----
#pragma unroll
        for (int l = 0; l < 2; l++) {
            int pos = tid + l * 256;
            int row = pos >> 2, g = pos & 3;
            size_t gi = (size_t)(n0 + row) * K + k0 + g * 8;
            uint4 vh = *(const uint4*)(Bh + gi);
            uint4 vl = *(const uint4*)(Bl + gi);
            int off = row * LDA + g * 8;
            *(uint4*)&sBh[off] = vh;
            *(uint4*)&sBl[off] = vl;
        }
        __syncthreads();
        // ---- compute: 2 k-steps of 16 ----
#pragma unroll
        for (int ks = 0; ks < 2; ks++) {
            const int kk = ks * 16;
            uint32_t afh[2][4], afl[2][4];
#pragma unroll
            for (int mt = 0; mt < 2; mt++) {
                int row = wm + mt * 16 + (lane & 15);
                int col = kk + (lane >> 4) * 8;
                LDSM4(afh[mt], ah_b + (uint32_t)(row * LDA + col) * 2);
                LDSM4(afl[mt], al_b + (uint32_t)(row * LDA + col) * 2);
            }
            uint32_t bfh[4][4], bfl[4][4];
#pragma unroll
            for (int np = 0; np < 4; np++) {
                int row = wn + np * 16 + (lane & 7) + ((lane >> 4) & 1) * 8;
                int col = kk + ((lane >> 3) & 1) * 8;
                LDSM4(bfh[np], bh_b + (uint32_t)(row * LDA + col) * 2);
                LDSM4(bfl[np], bl_b + (uint32_t)(row * LDA + col) * 2);
            }
#pragma unroll
            for (int mt = 0; mt < 2; mt++)
#pragma unroll
                for (int np = 0; np < 4; np++)
#pragma unroll
                    for (int sub = 0; sub < 2; sub++) {
                        int nt = np * 2 + sub;
                        mma_bf16(acc[mt][nt], afh[mt], &bfh[np][sub * 2]);
                        mma_bf16(acc[mt][nt], afl[mt], &bfh[np][sub * 2]);
                        mma_bf16(acc[mt][nt], afh[mt], &bfl[np][sub * 2]);
                    }
        }
        __syncthreads();
    }
    // ---- epilogue ----
#pragma unroll
    for (int mt = 0; mt < 2; mt++) {
        int row = m0 + wm + mt * 16 + (lane >> 2);
#pragma unroll
        for (int nt = 0; nt < 8; nt++) {
            int col = n0 + wn + nt * 8 + (lane & 3) * 2;
            float b0 = bias[col], b1 = bias[col + 1];
            float2 o0 = make_float2(acc[mt][nt][0] + b0, acc[mt][nt][1] + b1);
            float2 o1 = make_float2(acc[mt][nt][2] + b0, acc[mt][nt][3] + b1);
            if (RELU) {
                o0.x = fmaxf(o0.x, 0.f); o0.y = fmaxf(o0.y, 0.f);
                o1.x = fmaxf(o1.x, 0.f); o1.y = fmaxf(o1.y, 0.f);
            }
            if (row < M)     *(float2*)(C + (size_t)row * N + col) = o0;
            if (row + 8 < M) *(float2*)(C + (size_t)(row + 8) * N + col) = o1;
        }
    }
}

// ---------------- final layer ----------------
__global__ __launch_bounds__(256)
void final_kernel(const float* __restrict__ g3,
                  const float* __restrict__ sc, const float* __restrict__ sh,
                  const float* __restrict__ hw4, const float* __restrict__ hb4,
                  float* __restrict__ pen, float* __restrict__ logits) {
    __shared__ float w4s[256 * 16];
    __shared__ float at[16 * 256];
    int t = threadIdx.x;
    for (int i = t; i < 4096; i += 256) w4s[i] = hw4[i];
    long long r0 = (long long)blockIdx.x * 16;
#pragma unroll
    for (int i = 0; i < 16; i++) {
        float v = g3[(r0 + i) * 256 + t];
        v = fmaxf(fmaf(v, sc[t], sh[t]), 0.f);
        at[i * 256 + t] = v;
        pen[(r0 + i) * 256 + t] = v;
    }
    __syncthreads();
    int r = t >> 4, c = t & 15;
    float acc = hb4[c];
#pragma unroll 8
    for (int k = 0; k < 256; k++)
        acc = fmaf(at[r * 256 + k], w4s[k * 16 + c], acc);
    logits[(r0 + r) * 16 + c] = acc;
}

// ---------------- launch ----------------
extern "C" void kernel_launch(void* const* d_in, const int* in_sizes, int n_in,
                              void* d_out, int out_size) {
    const float* x   = (const float*)d_in[0];
    const void*  ei  = d_in[1];
    const float* w1  = (const float*)d_in[2];
    const float* b1  = (const float*)d_in[3];
    const float* wl  = (const float*)d_in[4];
    const float* bl  = (const float*)d_in[5];
    const float* wr  = (const float*)d_in[6];
    const float* hw1 = (const float*)d_in[7];
    const float* hb1 = (const float*)d_in[8];
    const float* ga1 = (const float*)d_in[9];
    const float* be1 = (const float*)d_in[10];
    const float* hw2 = (const float*)d_in[11];
    const float* hb2 = (const float*)d_in[12];
    const float* ga2 = (const float*)d_in[13];
    const float* be2 = (const float*)d_in[14];
    const float* hw3 = (const float*)d_in[15];
    const float* hb3 = (const float*)d_in[16];
    const float* ga3 = (const float*)d_in[17];
    const float* be3 = (const float*)d_in[18];
    const float* hw4 = (const float*)d_in[19];
    const float* hb4 = (const float*)d_in[20];

    float* out_logits = (float*)d_out;
    float* out_pen    = (float*)d_out + (size_t)NN * 16;
    float* out_feat   = (float*)d_out + (size_t)NN * (16 + 256);

    float *h0, *sums, *cnt, *p1, *p2, *p3, *sc, *sh;
    __nv_bfloat16 *b1h, *b1l, *b2h, *b2l, *b3h, *b3l, *b4h, *b4l, *b5h, *b5l;
    double *cs, *cq;
    int* flag;
    cudaGetSymbolAddress((void**)&h0,   g_h0);
    cudaGetSymbolAddress((void**)&sums, g_sums);
    cudaGetSymbolAddress((void**)&cnt,  g_cnt);
    cudaGetSymbolAddress((void**)&p1,   g_p1);
    cudaGetSymbolAddress((void**)&p2,   g_p2);
    cudaGetSymbolAddress((void**)&p3,   g_p3);
    cudaGetSymbolAddress((void**)&sc,   g_scale);
    cudaGetSymbolAddress((void**)&sh,   g_shift);
    cudaGetSymbolAddress((void**)&cs,   g_cs);
    cudaGetSymbolAddress((void**)&cq,   g_cq);
    cudaGetSymbolAddress((void**)&flag, g_is64);
    cudaGetSymbolAddress((void**)&b1h, g_b1h); cudaGetSymbolAddress((void**)&b1l, g_b1l);
    cudaGetSymbolAddress((void**)&b2h, g_b2h); cudaGetSymbolAddress((void**)&b2l, g_b2l);
    cudaGetSymbolAddress((void**)&b3h, g_b3h); cudaGetSymbolAddress((void**)&b3l, g_b3l);
    cudaGetSymbolAddress((void**)&b4h, g_b4h); cudaGetSymbolAddress((void**)&b4l, g_b4l);
    cudaGetSymbolAddress((void**)&b5h, g_b5h); cudaGetSymbolAddress((void**)&b5l, g_b5l);

    const int M = NN;
    const int MT = (M + 127) / 128;   // 782
    dim3 blk(256);

    // edge dtype detection
    set_flag<<<1, 1>>>(flag);
    detect64<<<16, 256>>>((const unsigned int*)ei, flag);

    // zero scatter accumulators
    zero_f<<<(NN * 128 / 4 + 255) / 256, blk>>>(sums, NN * 128);
    zero_f<<<(NN / 4 + 255) / 256, blk>>>(cnt, NN);

    // weight transpose+split (tiny)
    tsplit<<<32, blk>>>(w1, b1h, b1l, 64, 128);
    tsplit_cat<<<128, blk>>>(wl, wr, b2h, b2l);
    tsplit<<<128, blk>>>(hw1, b3h, b3l, 128, 256);
    tsplit<<<1024, blk>>>(hw2, b4h, b4l, 256, 1024);
    tsplit<<<1024, blk>>>(hw3, b5h, b5l, 1024, 256);

    // G1: h0 = relu(x@w1 + b1)   [M,64]@[64,128]
    mgemm<0, 1><<<dim3(1, MT), blk>>>(x, b1h, b1l, b1, h0, M, 64, 128,
                                      nullptr, nullptr, nullptr, nullptr);
    // edge scatter
    edge_kernel<<<EE / 8, blk>>>(ei, h0, sums, cnt, flag);

    // G2: out_feat = [aggr | h0] @ [wl; wr] + bl   [M,256]@[256,128]
    mgemm<2, 0><<<dim3(1, MT), blk>>>(sums, b2h, b2l, bl, out_feat, M, 256, 128,
                                      nullptr, nullptr, h0, cnt);
    // G3: p1 = out_feat @ hw1 + hb1   [M,128]@[128,256]
    mgemm<0, 0><<<dim3(2, MT), blk>>>(out_feat, b3h, b3l, hb1, p1, M, 128, 256,
                                      nullptr, nullptr, nullptr, nullptr);
    // BN1
    zstats<<<4, blk>>>(cs, cq);
    { dim3 g(1, 128); colstats<<<g, blk>>>(p1, 256, cs, cq); }
    fin_bn<<<1, 256>>>(cs, cq, ga1, be1, sc, sh, 256);

    // G4: p2 = relu(bn(p1)) @ hw2 + hb2   [M,256]@[256,1024]
    mgemm<1, 0><<<dim3(8, MT), blk>>>(p1, b4h, b4l, hb2, p2, M, 256, 1024,
                                      sc, sh, nullptr, nullptr);
    // BN2
    zstats<<<4, blk>>>(cs, cq);
    { dim3 g(4, 128); colstats<<<g, blk>>>(p2, 1024, cs, cq); }
    fin_bn<<<4, 256>>>(cs, cq, ga2, be2, sc, sh, 1024);

    // G5: p3 = relu(bn(p2)) @ hw3 + hb3   [M,1024]@[1024,256]
    mgemm<1, 0><<<dim3(2, MT), blk>>>(p2, b5h, b5l, hb3, p3, M, 1024, 256,
                                      sc, sh, nullptr, nullptr);
    // BN3
    zstats<<<4, blk>>>(cs, cq);
    { dim3 g(1, 128); colstats<<<g, blk>>>(p3, 256, cs, cq); }
    fin_bn<<<1, 256>>>(cs, cq, ga3, be3, sc, sh, 256);

    // final: penultimate + logits
    final_kernel<<<NN / 16, blk>>>(p3, sc, sh, hw4, hb4, out_pen, out_logits);
}

// round 4
// speedup vs baseline: 2.1786x; 1.3843x over previous
#include <cuda_runtime.h>
#include <cuda_bf16.h>
#include <cstdint>

// ---------------- problem constants ----------------
#define NN 100000
#define EE 1600000

// ---------------- scratch (device globals) ----------------
__device__ float  g_h0[(size_t)NN * 128];
__device__ float  g_sums[(size_t)NN * 128];
__device__ float  g_cnt[NN];
__device__ float  g_p1[(size_t)NN * 256];
__device__ float  g_p2[(size_t)NN * 1024];
__device__ float  g_p3[(size_t)NN * 256];
__device__ float  g_cs[1024];
__device__ float  g_cq[1024];
__device__ float  g_scale[1024];
__device__ float  g_shift[1024];
__device__ int    g_is64;
// packed split weights: [N][K/32][64] halves, chunk = [hi(32) | lo(32)]
__device__ __nv_bfloat16 g_b1[128 * 64 * 2];
__device__ __nv_bfloat16 g_b2[128 * 256 * 2];
__device__ __nv_bfloat16 g_b3[256 * 128 * 2];
__device__ __nv_bfloat16 g_b4[1024 * 256 * 2];
__device__ __nv_bfloat16 g_b5[256 * 1024 * 2];

// ---------------- helpers ----------------
__device__ __forceinline__ uint32_t smem_u32(const void* p) {
    uint32_t a;
    asm("{ .reg .u64 t; cvta.to.shared.u64 t, %1; cvt.u32.u64 %0, t; }" : "=r"(a) : "l"(p));
    return a;
}
#define LDSM4(R, addr) \
    asm volatile("ldmatrix.sync.aligned.m8n8.x4.shared.b16 {%0,%1,%2,%3}, [%4];" \
        : "=r"((R)[0]), "=r"((R)[1]), "=r"((R)[2]), "=r"((R)[3]) : "r"(addr))

__device__ __forceinline__ void mma_bf16(float* c, const uint32_t* a, const uint32_t* b) {
    asm volatile("mma.sync.aligned.m16n8k16.row.col.f32.bf16.bf16.f32 "
        "{%0,%1,%2,%3}, {%4,%5,%6,%7}, {%8,%9}, {%0,%1,%2,%3};"
        : "+f"(c[0]), "+f"(c[1]), "+f"(c[2]), "+f"(c[3])
        : "r"(a[0]), "r"(a[1]), "r"(a[2]), "r"(a[3]), "r"(b[0]), "r"(b[1]));
}
#define CP_A16(dst, src) \
    asm volatile("cp.async.ca.shared.global [%0], [%1], 16;" :: "r"(dst), "l"(src))
#define CP_A16Z(dst, src, ok) \
    asm volatile("{ .reg .pred p; .reg .s32 sz; setp.ne.u32 p, %2, 0;\n\t" \
        "selp.b32 sz, 16, 0, p;\n\t" \
        "cp.async.ca.shared.global [%0], [%1], 16, sz; }" \
        :: "r"(dst), "l"(src), "r"(ok))
#define CP_COMMIT() asm volatile("cp.async.commit_group;")
#define CP_WAIT0()  asm volatile("cp.async.wait_group 0;")

__device__ __forceinline__ void split_bf(float v, uint16_t& h, uint16_t& l) {
    __nv_bfloat16 hb = __float2bfloat16(v);
    __nv_bfloat16 lb = __float2bfloat16(v - __bfloat162float(hb));
    h = __bfloat16_as_ushort(hb);
    l = __bfloat16_as_ushort(lb);
}

// ---------------- small utility kernels ----------------
__global__ void zero_f(float* p, int n) {
    int i = (blockIdx.x * blockDim.x + threadIdx.x) * 4;
    if (i + 3 < n) { *(float4*)(p + i) = make_float4(0.f, 0.f, 0.f, 0.f); }
    else { for (; i < n; i++) p[i] = 0.f; }
}
__global__ void set_flag(int* f) { *f = 1; }
__global__ void detect64(const unsigned int* w, int* flag) {
    int t = blockIdx.x * blockDim.x + threadIdx.x;
    if (w[2 * t + 1] != 0u) atomicExch(flag, 0);
}
__global__ void zstats(float* cs, float* cq) {
    int i = blockIdx.x * blockDim.x + threadIdx.x;
    if (i < 1024) { cs[i] = 0.f; cq[i] = 0.f; }
}
// W[K,N] row-major -> packed [N][K/32][hi32|lo32]
__global__ void tsplit(const float* __restrict__ W, __nv_bfloat16* __restrict__ bp,
                       int K, int N) {
    int idx = blockIdx.x * blockDim.x + threadIdx.x;
    if (idx >= N * K) return;
    int n = idx / K, k = idx % K;
    uint16_t h, l;
    split_bf(W[(size_t)k * N + n], h, l);
    size_t base = ((size_t)n * (K >> 5) + (k >> 5)) * 64 + (k & 31);
    bp[base] = __ushort_as_bfloat16(h);
    bp[base + 32] = __ushort_as_bfloat16(l);
}
__global__ void tsplit_cat(const float* __restrict__ wl, const float* __restrict__ wr,
                           __nv_bfloat16* __restrict__ bp) {
    int idx = blockIdx.x * blockDim.x + threadIdx.x;   // < 128*256
    if (idx >= 128 * 256) return;
    int n = idx / 256, k = idx % 256;
    float v = (k < 128) ? wl[k * 128 + n] : wr[(k - 128) * 128 + n];
    uint16_t h, l;
    split_bf(v, h, l);
    size_t base = ((size_t)n * 8 + (k >> 5)) * 64 + (k & 31);
    bp[base] = __ushort_as_bfloat16(h);
    bp[base + 32] = __ushort_as_bfloat16(l);
}

// ---------------- edge scatter ----------------
__global__ void edge_kernel(const void* __restrict__ ei, const float* __restrict__ h0,
                            float* __restrict__ sums, float* __restrict__ cnt,
                            const int* __restrict__ flag) {
    int warp = (blockIdx.x * blockDim.x + threadIdx.x) >> 5;
    int lane = threadIdx.x & 31;
    if (warp >= EE) return;
    long long src, dst;
    if (*flag) {
        const long long* p = (const long long*)ei;
        src = p[warp]; dst = p[EE + warp];
    } else {
        const int* p = (const int*)ei;
        src = p[warp]; dst = p[EE + warp];
    }
    float4 v = *(const float4*)(h0 + src * 128 + lane * 4);
    float* d = sums + dst * 128 + lane * 4;
    asm volatile("red.global.add.v4.f32 [%0], {%1, %2, %3, %4};"
                 :: "l"(d), "f"(v.x), "f"(v.y), "f"(v.z), "f"(v.w) : "memory");
    if (lane == 0) atomicAdd(cnt + dst, 1.0f);
}

__global__ void fin_bn(const float* __restrict__ cs, const float* __restrict__ cq,
                       const float* __restrict__ gm, const float* __restrict__ bt,
                       float* __restrict__ sc, float* __restrict__ sh, int ncols) {
    int c = blockIdx.x * blockDim.x + threadIdx.x;
    if (c < ncols) {
        double mean = (double)cs[c] * (1.0 / (double)NN);
        double var  = (double)cq[c] * (1.0 / (double)NN) - mean * mean;
        if (var < 0.0) var = 0.0;
        float rstd = (float)(1.0 / sqrt(var + 1e-5));
        float s = gm[c] * rstd;
        sc[c] = s;
        sh[c] = bt[c] - (float)mean * s;
    }
}

// ---------------- pipelined mma.sync bf16x3 GEMM ----------------
// C[M,N] = T(A)[M,K] @ W + bias.  Bpk: packed split weights [N][K/32][hi32|lo32].
// MODE 0: plain | MODE 1: relu(a*sc+sh) | MODE 2: k<128: A(sums)/cnt; else aux(h0)
// CTA tile 128x128, BK=32, 8 warps (warp: 32 M x 64 N). STATS: accumulate col sums.
//
// dynamic smem layout:
//   [0, 36864)      rawA double buffer: 2 x 128 rows x 36 floats (144B stride)
//   [36864, 53248)  sA: 128 rows x 128B  (hi 64B | lo 64B, SW128 swizzled)
//   [53248, 86016)  sB double buffer: 2 x 128 rows x 128B (swizzled)
#define DSM_BYTES 86016

template<int MODE, int RELU, int STATS>
__global__ void __launch_bounds__(256, 1)
mgemm(const float* __restrict__ A, const __nv_bfloat16* __restrict__ Bpk,
      const float* __restrict__ bias, float* __restrict__ C,
      int M, int K, int N,
      const float* __restrict__ sc, const float* __restrict__ sh,
      const float* __restrict__ aux, const float* __restrict__ cnt,
      float* __restrict__ gs, float* __restrict__ gq) {
    extern __shared__ __align__(16) char dsm[];
    float* rawA = (float*)dsm;
    char* sAc = dsm + 36864;
    const uint32_t rawA_b = smem_u32(dsm);
    const uint32_t sA_b = rawA_b + 36864;
    const uint32_t sB_b = rawA_b + 53248;

    const int tid = threadIdx.x, lane = tid & 31, wid = tid >> 5;
    const int wm = (wid & 3) * 32, wn = (wid >> 2) * 64;
    const int m0 = blockIdx.y * 128, n0 = blockIdx.x * 128;
    const int nch = K >> 5;
    const int kc = K >> 5;

    float acc[2][8][4];
#pragma unroll
    for (int i = 0; i < 2; i++)
#pragma unroll
        for (int j = 0; j < 8; j++)
#pragma unroll
            for (int q = 0; q < 4; q++) acc[i][j][q] = 0.f;

    // ---- async issue of chunk c (A raw + B packed) ----
    auto issue = [&](int c) {
        const int buf = c & 1;
        const uint32_t ra = rawA_b + buf * 18432;
        const uint32_t bb = sB_b + buf * 16384;
        const int k0 = c << 5;
#pragma unroll
        for (int l = 0; l < 4; l++) {
            int pos = tid + l * 256;
            int row = pos >> 3, q = pos & 7;
            int grow = m0 + row;
            const char* srcA;
            if (MODE == 2) {
                if (k0 < 128) srcA = (const char*)(A + (size_t)grow * 128 + k0) + q * 16;
                else          srcA = (const char*)(aux + (size_t)grow * 128 + (k0 - 128)) + q * 16;
            } else {
                srcA = (const char*)(A + (size_t)grow * K + k0) + q * 16;
            }
            CP_A16Z(ra + row * 144 + q * 16, srcA, (grow < M) ? 1u : 0u);
            const char* srcB = (const char*)(Bpk + ((size_t)(n0 + row) * kc + c) * 64) + q * 16;
            CP_A16(bb + row * 128 + ((uint32_t)(q * 16) ^ (uint32_t)((row & 7) * 16)), srcB);
        }
        CP_COMMIT();
    };

    issue(0);

    for (int c = 0; c < nch; c++) {
        const int buf = c & 1;
        const int k0 = c << 5;
        CP_WAIT0();
        __syncthreads();                 // chunk-c data visible; compute(c-1) done
        // ---- split rawA[buf] -> sA (transform + bf16 hi/lo) ----
#pragma unroll
        for (int l = 0; l < 4; l++) {
            int pos = tid + l * 256;
            int row = pos >> 3, q = pos & 7;
            int grow = m0 + row;
            float4 v = *(const float4*)(rawA + buf * 4608 + row * 36 + q * 4);
            if (MODE == 1) {
                float4 s4 = *(const float4*)(sc + k0 + q * 4);
                float4 h4 = *(const float4*)(sh + k0 + q * 4);
                v.x = fmaxf(fmaf(v.x, s4.x, h4.x), 0.f);
                v.y = fmaxf(fmaf(v.y, s4.y, h4.y), 0.f);
                v.z = fmaxf(fmaf(v.z, s4.z, h4.z), 0.f);
                v.w = fmaxf(fmaf(v.w, s4.w, h4.w), 0.f);
            }
            if (MODE == 2 && k0 < 128) {
                float cv = (grow < M) ? cnt[grow] : 1.f;
                float ic = 1.f / fmaxf(cv, 1.f);
                v.x *= ic; v.y *= ic; v.z *= ic; v.w *= ic;
            }
            uint16_t hx, hy, hz, hw_, lx, ly, lz, lw;
            split_bf(v.x, hx, lx); split_bf(v.y, hy, ly);
            split_bf(v.z, hz, lz); split_bf(v.w, hw_, lw);
            uint2 hi2 = make_uint2((uint32_t)hx | ((uint32_t)hy << 16),
                                   (uint32_t)hz | ((uint32_t)hw_ << 16));
            uint2 lo2 = make_uint2((uint32_t)lx | ((uint32_t)ly << 16),
                                   (uint32_t)lz | ((uint32_t)lw << 16));
            uint32_t xr = (uint32_t)((row & 7) * 16);
            *(uint2*)(sAc + row * 128 + ((uint32_t)(q * 8) ^ xr)) = hi2;
            *(uint2*)(sAc + row * 128 + ((uint32_t)(64 + q * 8) ^ xr)) = lo2;
        }
        if (c + 1 < nch) issue(c + 1);   // overlaps next loads with compute below
        __syncthreads();                 // sA ready
        // ---- compute: 2 k-steps of 16 ----
        const uint32_t bb = sB_b + buf * 16384;
#pragma unroll
        for (int ks = 0; ks < 2; ks++) {
            const uint32_t kb = (uint32_t)(ks * 32);
            uint32_t afh[2][4], afl[2][4];
#pragma unroll
            for (int mt = 0; mt < 2; mt++) {
                int row = wm + mt * 16 + (lane & 15);
                uint32_t cb = kb + (uint32_t)((lane >> 4) * 16);
                uint32_t x = (uint32_t)((row & 7) * 16);
                LDSM4(afh[mt], sA_b + row * 128 + (cb ^ x));
                LDSM4(afl[mt], sA_b + row * 128 + ((cb + 64) ^ x));
            }
            uint32_t bfh[4][4], bfl[4][4];
#pragma unroll
            for (int np = 0; np < 4; np++) {
                int row = wn + np * 16 + (lane & 7) + ((lane >> 4) & 1) * 8;
                uint32_t cb = kb + (uint32_t)(((lane >> 3) & 1) * 16);
                uint32_t x = (uint32_t)((row & 7) * 16);
                LDSM4(bfh[np], bb + row * 128 + (cb ^ x));
                LDSM4(bfl[np], bb + row * 128 + ((cb + 64) ^ x));
            }
#pragma unroll
            for (int mt = 0; mt < 2; mt++)
#pragma unroll
                for (int np = 0; np < 4; np++)
#pragma unroll
                    for (int sub = 0; sub < 2; sub++) {
                        int nt = np * 2 + sub;
                        mma_bf16(acc[mt][nt], afh[mt], &bfh[np][sub * 2]);
                        mma_bf16(acc[mt][nt], afl[mt], &bfh[np][sub * 2]);
                        mma_bf16(acc[mt][nt], afh[mt], &bfl[np][sub * 2]);
                    }
        }
        __syncthreads();                 // protect sA/sB before next split/issue
    }

    // ---- epilogue: write C (+ optional fused column stats) ----
    float* ssum = (float*)dsm;           // reuse: 128 s + 128 q
    if (STATS) {
        if (tid < 256) ssum[tid] = 0.f;
        __syncthreads();
    }
#pragma unroll
    for (int mt = 0; mt < 2; mt++) {
        int row = m0 + wm + mt * 16 + (lane >> 2);
#pragma unroll
        for (int nt = 0; nt < 8; nt++) {
            int col = n0 + wn + nt * 8 + (lane & 3) * 2;
            float b0 = bias[col], b1 = bias[col + 1];
            float2 o0 = make_float2(acc[mt][nt][0] + b0, acc[mt][nt][1] + b1);
            float2 o1 = make_float2(acc[mt][nt][2] + b0, acc[mt][nt][3] + b1);
            if (RELU) {
                o0.x = fmaxf(o0.x, 0.f); o0.y = fmaxf(o0.y, 0.f);
                o1.x = fmaxf(o1.x, 0.f); o1.y = fmaxf(o1.y, 0.f);
            }
            if (row < M)     *(float2*)(C + (size_t)row * N + col) = o0;
            if (row + 8 < M) *(float2*)(C + (size_t)(row + 8) * N + col) = o1;
        }
    }
    if (STATS) {
#pragma unroll
        for (int nt = 0; nt < 8; nt++) {
            int colr = wn + nt * 8 + (lane & 3) * 2;
            float b0 = bias[n0 + colr], b1 = bias[n0 + colr + 1];
            float s0 = 0.f, s1 = 0.f, q0 = 0.f, q1 = 0.f;
#pragma unroll
            for (int mt = 0; mt < 2; mt++) {
                int r = m0 + wm + mt * 16 + (lane >> 2);
                float ok0 = (r < M) ? 1.f : 0.f;
                float ok1 = (r + 8 < M) ? 1.f : 0.f;
                float v00 = (acc[mt][nt][0] + b0) * ok0;
                float v01 = (acc[mt][nt][1] + b1) * ok0;
                float v10 = (acc[mt][nt][2] + b0) * ok1;
                float v11 = (acc[mt][nt][3] + b1) * ok1;
                s0 += v00 + v10; s1 += v01 + v11;
                q0 += v00 * v00 + v10 * v10;
                q1 += v01 * v01 + v11 * v11;
            }
#pragma unroll
            for (int d = 4; d < 32; d <<= 1) {
                s0 += __shfl_xor_sync(0xFFFFFFFFu, s0, d);
                s1 += __shfl_xor_sync(0xFFFFFFFFu, s1, d);
                q0 += __shfl_xor_sync(0xFFFFFFFFu, q0, d);
                q1 += __shfl_xor_sync(0xFFFFFFFFu, q1, d);
            }
            if (lane < 4) {
                atomicAdd(&ssum[colr], s0);
                atomicAdd(&ssum[colr + 1], s1);
                atomicAdd(&ssum[128 + colr], q0);
                atomicAdd(&ssum[128 + colr + 1], q1);
            }
        }
        __syncthreads();
        if (tid < 128)       atomicAdd(&gs[n0 + tid], ssum[tid]);
        else if (tid < 256)  atomicAdd(&gq[n0 + tid - 128], ssum[tid]);
    }
}

// ---------------- final layer ----------------
__global__ __launch_bounds__(256)
void final_kernel(const float* __restrict__ g3,
                  const float* __restrict__ sc, const float* __restrict__ sh,
                  const float* __restrict__ hw4, const float* __restrict__ hb4,
                  float* __restrict__ pen, float* __restrict__ logits) {
    __shared__ float w4s[256 * 16];
    __shared__ float at[16 * 256];
    int t = threadIdx.x;
    for (int i = t; i < 4096; i += 256) w4s[i] = hw4[i];
    long long r0 = (long long)blockIdx.x * 16;
#pragma unroll
    for (int i = 0; i < 16; i++) {
        float v = g3[(r0 + i) * 256 + t];
        v = fmaxf(fmaf(v, sc[t], sh[t]), 0.f);
        at[i * 256 + t] = v;
        pen[(r0 + i) * 256 + t] = v;
    }
    __syncthreads();
    int r = t >> 4, c = t & 15;
    float acc = hb4[c];
#pragma unroll 8
    for (int k = 0; k < 256; k++)
        acc = fmaf(at[r * 256 + k], w4s[k * 16 + c], acc);
    logits[(r0 + r) * 16 + c] = acc;
}

// ---------------- launch ----------------
extern "C" void kernel_launch(void* const* d_in, const int* in_sizes, int n_in,
                              void* d_out, int out_size) {
    const float* x   = (const float*)d_in[0];
    const void*  ei  = d_in[1];
    const float* w1  = (const float*)d_in[2];
    const float* b1  = (const float*)d_in[3];
    const float* wl  = (const float*)d_in[4];
    const float* bl  = (const float*)d_in[5];
    const float* wr  = (const float*)d_in[6];
    const float* hw1 = (const float*)d_in[7];
    const float* hb1 = (const float*)d_in[8];
    const float* ga1 = (const float*)d_in[9];
    const float* be1 = (const float*)d_in[10];
    const float* hw2 = (const float*)d_in[11];
    const float* hb2 = (const float*)d_in[12];
    const float* ga2 = (const float*)d_in[13];
    const float* be2 = (const float*)d_in[14];
    const float* hw3 = (const float*)d_in[15];
    const float* hb3 = (const float*)d_in[16];
    const float* ga3 = (const float*)d_in[17];
    const float* be3 = (const float*)d_in[18];
    const float* hw4 = (const float*)d_in[19];
    const float* hb4 = (const float*)d_in[20];

    float* out_logits = (float*)d_out;
    float* out_pen    = (float*)d_out + (size_t)NN * 16;
    float* out_feat   = (float*)d_out + (size_t)NN * (16 + 256);

    float *h0, *sums, *cnt, *p1, *p2, *p3, *sc, *sh, *cs, *cq;
    __nv_bfloat16 *b1p, *b2p, *b3p, *b4p, *b5p;
    int* flag;
    cudaGetSymbolAddress((void**)&h0,   g_h0);
    cudaGetSymbolAddress((void**)&sums, g_sums);
    cudaGetSymbolAddress((void**)&cnt,  g_cnt);
    cudaGetSymbolAddress((void**)&p1,   g_p1);
    cudaGetSymbolAddress((void**)&p2,   g_p2);
    cudaGetSymbolAddress((void**)&p3,   g_p3);
    cudaGetSymbolAddress((void**)&sc,   g_scale);
    cudaGetSymbolAddress((void**)&sh,   g_shift);
    cudaGetSymbolAddress((void**)&cs,   g_cs);
    cudaGetSymbolAddress((void**)&cq,   g_cq);
    cudaGetSymbolAddress((void**)&flag, g_is64);
    cudaGetSymbolAddress((void**)&b1p, g_b1);
    cudaGetSymbolAddress((void**)&b2p, g_b2);
    cudaGetSymbolAddress((void**)&b3p, g_b3);
    cudaGetSymbolAddress((void**)&b4p, g_b4);
    cudaGetSymbolAddress((void**)&b5p, g_b5);

    const int M = NN;
    const int MT = (M + 127) / 128;   // 782
    dim3 blk(256);

    cudaFuncSetAttribute(mgemm<0,1,0>, cudaFuncAttributeMaxDynamicSharedMemorySize, DSM_BYTES);
    cudaFuncSetAttribute(mgemm<2,0,0>, cudaFuncAttributeMaxDynamicSharedMemorySize, DSM_BYTES);
    cudaFuncSetAttribute(mgemm<0,0,1>, cudaFuncAttributeMaxDynamicSharedMemorySize, DSM_BYTES);
    cudaFuncSetAttribute(mgemm<1,0,1>, cudaFuncAttributeMaxDynamicSharedMemorySize, DSM_BYTES);

    // edge dtype detection
    set_flag<<<1, 1>>>(flag);
    detect64<<<16, 256>>>((const unsigned int*)ei, flag);

    // zero scatter accumulators
    zero_f<<<(NN * 128 / 4 + 255) / 256, blk>>>(sums, NN * 128);
    zero_f<<<(NN / 4 + 255) / 256, blk>>>(cnt, NN);

    // weight transpose+split+pack (tiny)
    tsplit<<<32, blk>>>(w1, b1p, 64, 128);
    tsplit_cat<<<128, blk>>>(wl, wr, b2p);
    tsplit<<<128, blk>>>(hw1, b3p, 128, 256);
    tsplit<<<1024, blk>>>(hw2, b4p, 256, 1024);
    tsplit<<<1024, blk>>>(hw3, b5p, 1024, 256);

    // G1: h0 = relu(x@w1 + b1)
    mgemm<0,1,0><<<dim3(1, MT), blk, DSM_BYTES>>>(x, b1p, b1, h0, M, 64, 128,
        nullptr, nullptr, nullptr, nullptr, nullptr, nullptr);
    // edge scatter
    edge_kernel<<<EE / 8, blk>>>(ei, h0, sums, cnt, flag);
    // G2: out_feat = [aggr | h0] @ [wl; wr] + bl
    mgemm<2,0,0><<<dim3(1, MT), blk, DSM_BYTES>>>(sums, b2p, bl, out_feat, M, 256, 128,
        nullptr, nullptr, h0, cnt, nullptr, nullptr);
    // G3 (+stats): p1 = out_feat @ hw1 + hb1
    zstats<<<4, blk>>>(cs, cq);
    mgemm<0,0,1><<<dim3(2, MT), blk, DSM_BYTES>>>(out_feat, b3p, hb1, p1, M, 128, 256,
        nullptr, nullptr, nullptr, nullptr, cs, cq);
    fin_bn<<<1, 256>>>(cs, cq, ga1, be1, sc, sh, 256);
    // G4 (+stats): p2 = relu(bn(p1)) @ hw2 + hb2
    zstats<<<4, blk>>>(cs, cq);
    mgemm<1,0,1><<<dim3(8, MT), blk, DSM_BYTES>>>(p1, b4p, hb2, p2, M, 256, 1024,
        sc, sh, nullptr, nullptr, cs, cq);
    fin_bn<<<4, 256>>>(cs, cq, ga2, be2, sc, sh, 1024);
    // G5 (+stats): p3 = relu(bn(p2)) @ hw3 + hb3
    zstats<<<4, blk>>>(cs, cq);
    mgemm<1,0,1><<<dim3(2, MT), blk, DSM_BYTES>>>(p2, b5p, hb3, p3, M, 1024, 256,
        sc, sh, nullptr, nullptr, cs, cq);
    fin_bn<<<1, 256>>>(cs, cq, ga3, be3, sc, sh, 256);
    // final: penultimate + logits
    final_kernel<<<NN / 16, blk>>>(p3, sc, sh, hw4, hb4, out_pen, out_logits);
}